// round 5
// baseline (speedup 1.0000x reference)
#include <cuda_runtime.h>
#include <cstdint>

#define B_ROWS 16384
#define C_COLS 4096

// Scratch (allocation-free). Zero-initialized at module load; the loss kernel
// resets each bin after consuming it, so every kernel_launch (correctness call
// and each graph replay) starts from an all-zero bin array. Deterministic:
// no call-count dependence, invariant maintained by every complete launch.
__device__ unsigned long long g_bins[B_ROWS];

// Kernel 1: deterministic last-write-wins scatter + output zeroing.
// Pack (j << 32) | float_bits(v[index[j]]) and atomicMax per bin.
// Highest j wins (serial-loop last-write-wins semantics). Untouched bins stay
// 0 -> weight 0.0f. Thread 0 also zeroes d_out (poisoned 0xAA by harness).
__global__ void scatter_kernel(const int* __restrict__ index,
                               const float* __restrict__ v,
                               int v_n,
                               float* __restrict__ out) {
    int j = blockIdx.x * blockDim.x + threadIdx.x;
    if (j == 0) out[0] = 0.0f;
    if (j >= B_ROWS) return;
    unsigned idx = (unsigned)index[j];
    if (idx >= (unsigned)v_n) idx = 0u;  // sanitize: wrong answer > fault
    unsigned pos = idx & (B_ROWS - 1);   // B_ROWS is a power of two
    unsigned vb = __float_as_uint(v[idx]);
    unsigned long long packed =
        ((unsigned long long)(unsigned)j << 32) | (unsigned long long)vb;
    atomicMax(&g_bins[pos], packed);
}

// Kernel 2: per-row weighted cross-entropy, fused accumulation.
// One block per row, 128 threads. Early-exits zero-weight rows (skips the
// 16KB row read). Resets its bin for the next replay. Non-zero rows
// atomicAdd(loss * w / B) directly into out[0].
__global__ void __launch_bounds__(128) loss_kernel(const float* __restrict__ input,
                                                   const int* __restrict__ target,
                                                   float* __restrict__ out) {
    const int row = blockIdx.x;
    const int tid = threadIdx.x;

    __shared__ float sh_w;
    __shared__ float sh_m[4];
    __shared__ float sh_s[4];

    // tid0 reads the bin, resets it (self-resetting invariant), broadcasts w.
    if (tid == 0) {
        unsigned long long b = g_bins[row];
        g_bins[row] = 0ull;
        sh_w = __uint_as_float((unsigned)(b & 0xffffffffull));
    }
    __syncthreads();
    const float w = sh_w;
    if (w == 0.0f) return;  // contributes 0 to the sum; no write needed

    const float4* rowp = (const float4*)(input + (size_t)row * C_COLS);

    // Online (streaming) logsumexp per thread. 8 fully-unrolled iterations,
    // loads front-batched by ptxas (high MLP).
    float m = -3.402823466e38f;  // -FLT_MAX
    float s = 0.0f;
#pragma unroll
    for (int i = tid; i < C_COLS / 4; i += 128) {
        float4 x = rowp[i];
        float mx = fmaxf(fmaxf(x.x, x.y), fmaxf(x.z, x.w));
        if (mx > m) {
            s *= __expf(m - mx);
            m = mx;
        }
        s += __expf(x.x - m) + __expf(x.y - m) + __expf(x.z - m) + __expf(x.w - m);
    }

    // Warp-level (m, s) reduction.
#pragma unroll
    for (int off = 16; off > 0; off >>= 1) {
        float om = __shfl_xor_sync(0xffffffffu, m, off);
        float os = __shfl_xor_sync(0xffffffffu, s, off);
        float nm = fmaxf(m, om);
        s = s * __expf(m - nm) + os * __expf(om - nm);
        m = nm;
    }

    const int warp = tid >> 5;
    const int lane = tid & 31;
    if (lane == 0) {
        sh_m[warp] = m;
        sh_s[warp] = s;
    }
    __syncthreads();

    if (tid == 0) {
        float M = sh_m[0];
        float S = sh_s[0];
#pragma unroll
        for (int k = 1; k < 4; k++) {
            float om = sh_m[k], os = sh_s[k];
            float nm = fmaxf(M, om);
            S = S * __expf(M - nm) + os * __expf(om - nm);
            M = nm;
        }
        unsigned t = (unsigned)target[row];
        if (t >= (unsigned)C_COLS) t = 0u;  // sanitize, never fault
        float xt = input[(size_t)row * C_COLS + (size_t)t];
        float loss = (logf(S) + M - xt) * w * (1.0f / (float)B_ROWS);
        atomicAdd(out, loss);
    }
}

extern "C" void kernel_launch(void* const* d_in, const int* in_sizes, int n_in,
                              void* d_out, int out_size) {
    const float* input  = (const float*)d_in[0];  // [16384, 4096] f32
    const float* v      = (const float*)d_in[1];  // [1000000] f32
    const int*   target = (const int*)d_in[2];    // [16384] i32 (x64-disabled JAX)
    const int*   index  = (const int*)d_in[3];    // [16384] i32
    float* out = (float*)d_out;
    const int v_n = in_sizes[1];

    scatter_kernel<<<(B_ROWS + 255) / 256, 256>>>(index, v, v_n, out);
    loss_kernel<<<B_ROWS, 128>>>(input, target, out);
}

// round 10
// speedup vs baseline: 1.9518x; 1.9518x over previous
#include <cuda_runtime.h>
#include <cstdint>

#define B_ROWS 16384
#define C_COLS 4096
#define ACC_SLOTS 64

// Scratch (allocation-free). Zero-initialized at module load; finalize_kernel
// re-zeroes both arrays at the end of every launch, so each kernel_launch
// (correctness call and every graph replay) starts from the same state.
__device__ unsigned long long g_bins[B_ROWS];
__device__ float g_accum[ACC_SLOTS];

// Kernel 1: deterministic last-write-wins scatter.
// Pack (j << 32) | float_bits(v[index[j]]) and atomicMax per bin.
// Highest j wins (serial last-write-wins semantics). Untouched bins stay
// 0 -> weight 0.0f. index/target are int32 (JAX x64-disabled).
__global__ void scatter_kernel(const int* __restrict__ index,
                               const float* __restrict__ v,
                               int v_n) {
    int j = blockIdx.x * blockDim.x + threadIdx.x;
    if (j >= B_ROWS) return;
    unsigned idx = (unsigned)index[j];
    if (idx >= (unsigned)v_n) idx = 0u;  // sanitize: wrong answer > fault
    unsigned pos = idx & (B_ROWS - 1);   // B_ROWS is a power of two
    unsigned vb = __float_as_uint(v[idx]);
    unsigned long long packed =
        ((unsigned long long)(unsigned)j << 32) | (unsigned long long)vb;
    atomicMax(&g_bins[pos], packed);
}

// Kernel 2: per-row weighted cross-entropy. One block per row, 128 threads.
// R3-proven prologue: every thread does the uniform bin load and branches
// immediately — no syncthreads, no shared broadcast, no store in the exit
// path. Zero-weight rows skip their 16KB read entirely.
__global__ void __launch_bounds__(128) loss_kernel(const float* __restrict__ input,
                                                   const int* __restrict__ target) {
    const int row = blockIdx.x;
    const int tid = threadIdx.x;

    const float w = __uint_as_float((unsigned)(g_bins[row] & 0xffffffffull));
    if (w == 0.0f) return;

    const float4* rowp = (const float4*)(input + (size_t)row * C_COLS);

    // Online (streaming) logsumexp per thread.
    float m = -3.402823466e38f;  // -FLT_MAX
    float s = 0.0f;
#pragma unroll
    for (int i = tid; i < C_COLS / 4; i += 128) {
        float4 x = rowp[i];
        float mx = fmaxf(fmaxf(x.x, x.y), fmaxf(x.z, x.w));
        if (mx > m) {
            s *= __expf(m - mx);
            m = mx;
        }
        s += __expf(x.x - m) + __expf(x.y - m) + __expf(x.z - m) + __expf(x.w - m);
    }

    // Warp-level (m, s) reduction.
#pragma unroll
    for (int off = 16; off > 0; off >>= 1) {
        float om = __shfl_xor_sync(0xffffffffu, m, off);
        float os = __shfl_xor_sync(0xffffffffu, s, off);
        float nm = fmaxf(m, om);
        s = s * __expf(m - nm) + os * __expf(om - nm);
        m = nm;
    }

    // Cross-warp combine (4 warps).
    __shared__ float sh_m[4];
    __shared__ float sh_s[4];
    const int warp = tid >> 5;
    const int lane = tid & 31;
    if (lane == 0) {
        sh_m[warp] = m;
        sh_s[warp] = s;
    }
    __syncthreads();

    if (tid == 0) {
        float M = sh_m[0];
        float S = sh_s[0];
#pragma unroll
        for (int k = 1; k < 4; k++) {
            float om = sh_m[k], os = sh_s[k];
            float nm = fmaxf(M, om);
            S = S * __expf(M - nm) + os * __expf(om - nm);
            M = nm;
        }
        unsigned t = (unsigned)target[row];
        if (t >= (unsigned)C_COLS) t = 0u;  // sanitize, never fault
        float xt = input[(size_t)row * C_COLS + (size_t)t];
        // Spread atomics over 64 distinct L2 addresses (no same-address
        // serialization; per-CTA-distinct atomics are ~63x faster).
        atomicAdd(&g_accum[row & (ACC_SLOTS - 1)], (logf(S) + M - xt) * w);
    }
}

// Kernel 3: finalize. 64 blocks x 256 threads.
// Every block re-zeroes its slice of g_bins (16384 = 64*256) for the next
// replay. Block 0 additionally reduces the 64 accumulator slots, writes
// out[0] = sum / B, and resets g_accum.
__global__ void __launch_bounds__(256) finalize_kernel(float* __restrict__ out) {
    const int i = blockIdx.x * 256 + threadIdx.x;
    if (i < B_ROWS) g_bins[i] = 0ull;

    if (blockIdx.x != 0) return;

    __shared__ float sh[ACC_SLOTS];
    if (threadIdx.x < ACC_SLOTS) sh[threadIdx.x] = g_accum[threadIdx.x];
    __syncthreads();
    if (threadIdx.x < ACC_SLOTS) g_accum[threadIdx.x] = 0.0f;
    if (threadIdx.x == 0) {
        float t = 0.0f;
#pragma unroll
        for (int k = 0; k < ACC_SLOTS; k++) t += sh[k];
        out[0] = t * (1.0f / (float)B_ROWS);
    }
}

extern "C" void kernel_launch(void* const* d_in, const int* in_sizes, int n_in,
                              void* d_out, int out_size) {
    const float* input  = (const float*)d_in[0];  // [16384, 4096] f32
    const float* v      = (const float*)d_in[1];  // [1000000] f32
    const int*   target = (const int*)d_in[2];    // [16384] i32
    const int*   index  = (const int*)d_in[3];    // [16384] i32
    float* out = (float*)d_out;
    const int v_n = in_sizes[1];

    scatter_kernel<<<(B_ROWS + 255) / 256, 256>>>(index, v, v_n);
    loss_kernel<<<B_ROWS, 128>>>(input, target);
    finalize_kernel<<<ACC_SLOTS, 256>>>(out);
}